// round 2
// baseline (speedup 1.0000x reference)
#include <cuda_runtime.h>
#include <cuda_bf16.h>

// CLUB loss, single-pass formulation.
//   result = ( -0.5*P + 0.5/N * sum_d [ X2_d*S_d - 2*X_d*T_d ] ) / N
// with  P    = sum_{i,d} (x^2 - 2*x*mu) * exp(-lv)
//       X_d  = sum_i x,   X2_d = sum_i x^2
//       S_d  = sum_i exp(-lv),   T_d = sum_i mu*exp(-lv)
// (The mu^2 terms cancel between positive and negative.)
//
// Shapes: x (16,512,32,32) f32, p_mu (16384,512) f32, p_logvar (16384,512) f32.
// N = 16384, D = 512, HW = 1024.

#define NB   16
#define DD   512
#define HW   1024
#define NTOK (NB * HW)          // 16384

// Grid decomposition for kernel 1:
//  dchunk  : 8  chunks of 64 features   (bid & 7)
//  slice   : 128 slices of 128 tokens   (bid >> 3)
//  grid    = 1024 blocks x 256 threads
#define DCHUNK 64
#define SLICE_TOK 128
#define GROUP_TOK 64            // tokens staged per smem fill
#define NSLICE 128

// Stateless per-launch scratch (fully overwritten by kernel 1 each launch,
// fully consumed by kernel 2 — no cross-replay invariant).
// gPart[a][d][slice]: a in {0=X,1=X2,2=S,3=T}
__device__ float gPart[4 * DD * NSLICE];   // 1 MB
__device__ float gP[1024];                 // per-block scalar partials

__global__ __launch_bounds__(256) void club_main_kernel(
    const float* __restrict__ x,
    const float* __restrict__ pmu,
    const float* __restrict__ plv)
{
    __shared__ float xs[GROUP_TOK][65];    // [d_in_chunk][token], pitch 65 -> conflict-free reads
    __shared__ float red[4][8][DCHUNK];    // cross-warp reduction buffer
    __shared__ float spc[8];               // per-warp scalar partials

    const int tid  = threadIdx.x;
    const int w    = tid >> 5;
    const int lane = tid & 31;
    const int bid  = blockIdx.x;

    const int dc    = (bid & 7) << 6;      // feature-chunk base (0..448)
    const int slice = bid >> 3;            // token-slice index  (0..127)
    const int i0    = slice << 7;          // token-slice base   (0..16256)

    float sX[2]  = {0.f, 0.f};
    float sXX[2] = {0.f, 0.f};
    float sS[2]  = {0.f, 0.f};
    float sT[2]  = {0.f, 0.f};
    float accP   = 0.f;

    #pragma unroll
    for (int g = 0; g < SLICE_TOK / GROUP_TOK; ++g) {
        const int tg0 = i0 + (g << 6);         // first token of this group
        const int b   = tg0 >> 10;             // batch index (group never crosses b)
        const int hwb = tg0 & 1023;            // hw offset within plane
        const float* xb = x + ((size_t)((b << 9) + dc) << 10) + hwb;  // x[b, dc, hwb]

        // ---- stage x tile (64 d-rows x 64 tokens) into smem ----
        #pragma unroll
        for (int k = 0; k < 4; ++k) {
            int q   = tid + (k << 8);
            int row = q >> 4;                  // d within chunk
            int c4  = q & 15;                  // float4 column
            float4 v = *reinterpret_cast<const float4*>(xb + row * HW + (c4 << 2));
            xs[row][(c4 << 2) + 0] = v.x;
            xs[row][(c4 << 2) + 1] = v.y;
            xs[row][(c4 << 2) + 2] = v.z;
            xs[row][(c4 << 2) + 3] = v.w;
        }
        __syncthreads();

        // ---- main accumulation: warp w handles tokens [w*8, w*8+8),
        //      lane owns d = dc+lane and dc+lane+32 ----
        #pragma unroll
        for (int t = 0; t < 8; ++t) {
            const int tl = (w << 3) + t;              // token local to group
            const int i  = tg0 + tl;                  // global token
            const float* mrow = pmu + (size_t)i * DD + dc + lane;
            const float* lrow = plv + (size_t)i * DD + dc + lane;
            #pragma unroll
            for (int c = 0; c < 2; ++c) {
                const float mu = mrow[c << 5];        // coalesced 128B/warp
                const float lv = lrow[c << 5];
                const float xv = xs[lane + (c << 5)][tl];
                const float iv = __expf(-lv);
                const float xx = xv * xv;
                const float e  = fmaf(xv * mu, -2.0f, xx);   // x^2 - 2*x*mu
                accP   = fmaf(e, iv, accP);
                sS[c] += iv;
                sT[c]  = fmaf(mu, iv, sT[c]);
                sX[c] += xv;
                sXX[c] += xx;
            }
        }
        __syncthreads();
    }

    // ---- cross-warp reduce per-d accumulators ----
    #pragma unroll
    for (int c = 0; c < 2; ++c) {
        red[0][w][lane + (c << 5)] = sX[c];
        red[1][w][lane + (c << 5)] = sXX[c];
        red[2][w][lane + (c << 5)] = sS[c];
        red[3][w][lane + (c << 5)] = sT[c];
    }
    // warp-reduce scalar
    #pragma unroll
    for (int o = 16; o; o >>= 1) accP += __shfl_xor_sync(0xffffffffu, accP, o);
    if (lane == 0) spc[w] = accP;
    __syncthreads();

    {
        const int a  = tid >> 6;      // which accumulator (0..3)
        const int dd = tid & 63;      // d within chunk
        float s = 0.f;
        #pragma unroll
        for (int ww = 0; ww < 8; ++ww) s += red[a][ww][dd];
        gPart[((a * DD) + dc + dd) * NSLICE + slice] = s;
    }
    if (tid == 0) {
        float s = 0.f;
        #pragma unroll
        for (int ww = 0; ww < 8; ++ww) s += spc[ww];
        gP[bid] = s;
    }
}

__global__ __launch_bounds__(512) void club_final_kernel(float* __restrict__ out)
{
    __shared__ double sd[512];
    __shared__ double sp[512];
    const int tid = threadIdx.x;   // tid == feature d

    // Reduce the 128 slice-partials for each of the 4 accumulators in double.
    double A[4];
    #pragma unroll
    for (int a = 0; a < 4; ++a) {
        const float* p = &gPart[((a * DD) + tid) * NSLICE];
        double s = 0.0;
        #pragma unroll 4
        for (int sl = 0; sl < NSLICE; ++sl) s += (double)p[sl];
        A[a] = s;
    }
    const double X = A[0], XX = A[1], S = A[2], T = A[3];

    sd[tid] = XX * S - 2.0 * X * T;
    sp[tid] = (double)gP[tid] + (double)gP[tid + 512];
    __syncthreads();

    #pragma unroll
    for (int o = 256; o; o >>= 1) {
        if (tid < o) { sd[tid] += sd[tid + o]; sp[tid] += sp[tid + o]; }
        __syncthreads();
    }
    if (tid == 0) {
        const double N = (double)NTOK;
        const double res = (-0.5 * sp[0] + 0.5 * sd[0] / N) / N;
        out[0] = (float)res;
    }
}

extern "C" void kernel_launch(void* const* d_in, const int* in_sizes, int n_in,
                              void* d_out, int out_size)
{
    const float* x   = (const float*)d_in[0];
    const float* pmu = (const float*)d_in[1];
    const float* plv = (const float*)d_in[2];
    float* out = (float*)d_out;

    club_main_kernel<<<1024, 256>>>(x, pmu, plv);
    club_final_kernel<<<1, 512>>>(out);
}

// round 3
// speedup vs baseline: 5.0449x; 5.0449x over previous
#include <cuda_runtime.h>
#include <cuda_bf16.h>

// CLUB loss, single-pass formulation.
//   result = ( -0.5*P + 0.5/N * sum_d [ X2_d*S_d - 2*X_d*T_d ] ) / N
// with  P    = sum_{i,d} (x^2 - 2*x*mu) * exp(-lv)
//       X_d  = sum_i x,   X2_d = sum_i x^2
//       S_d  = sum_i exp(-lv),   T_d = sum_i mu*exp(-lv)
// (The mu^2 terms cancel between positive and negative.)
//
// Shapes: x (16,512,32,32) f32, p_mu (16384,512) f32, p_logvar (16384,512) f32.
// N = 16384, D = 512, HW = 1024.

#define NB   16
#define DD   512
#define HW   1024
#define NTOK (NB * HW)          // 16384

#define DCHUNK 64
#define SLICE_TOK 128
#define GROUP_TOK 64
#define NSLICE 128

// Stateless per-launch scratch (fully overwritten each launch).
// gPart layout: [a][slice][d]  (d innermost -> coalesced stage-2 reads)
__device__ float  gPart[4 * NSLICE * DD];   // 1 MB
__device__ float  gP[1024];                 // per-block scalar partials
__device__ double gAcc[4 * DD];             // stage-2 output (doubles)

__global__ __launch_bounds__(256) void club_main_kernel(
    const float* __restrict__ x,
    const float* __restrict__ pmu,
    const float* __restrict__ plv)
{
    __shared__ float xs[GROUP_TOK][65];    // [d_in_chunk][token], conflict-free reads
    __shared__ float red[4][8][DCHUNK];
    __shared__ float spc[8];

    const int tid  = threadIdx.x;
    const int w    = tid >> 5;
    const int lane = tid & 31;
    const int bid  = blockIdx.x;

    const int dc    = (bid & 7) << 6;      // feature-chunk base (0..448)
    const int slice = bid >> 3;            // token-slice index  (0..127)
    const int i0    = slice << 7;          // token-slice base

    float sX[2]  = {0.f, 0.f};
    float sXX[2] = {0.f, 0.f};
    float sS[2]  = {0.f, 0.f};
    float sT[2]  = {0.f, 0.f};
    float accP   = 0.f;

    #pragma unroll
    for (int g = 0; g < SLICE_TOK / GROUP_TOK; ++g) {
        const int tg0 = i0 + (g << 6);
        const int b   = tg0 >> 10;
        const int hwb = tg0 & 1023;
        const float* xb = x + ((size_t)((b << 9) + dc) << 10) + hwb;  // x[b, dc, hwb]

        // ---- stage x tile (64 d-rows x 64 tokens) into smem ----
        #pragma unroll
        for (int k = 0; k < 4; ++k) {
            int q   = tid + (k << 8);
            int row = q >> 4;
            int c4  = q & 15;
            float4 v = *reinterpret_cast<const float4*>(xb + row * HW + (c4 << 2));
            xs[row][(c4 << 2) + 0] = v.x;
            xs[row][(c4 << 2) + 1] = v.y;
            xs[row][(c4 << 2) + 2] = v.z;
            xs[row][(c4 << 2) + 3] = v.w;
        }
        __syncthreads();

        // ---- warp w handles tokens [w*8, w*8+8); lane owns d=dc+lane, dc+lane+32 ----
        #pragma unroll
        for (int t = 0; t < 8; ++t) {
            const int tl = (w << 3) + t;
            const int i  = tg0 + tl;
            const float* mrow = pmu + (size_t)i * DD + dc + lane;
            const float* lrow = plv + (size_t)i * DD + dc + lane;
            #pragma unroll
            for (int c = 0; c < 2; ++c) {
                const float mu = mrow[c << 5];
                const float lv = lrow[c << 5];
                const float xv = xs[lane + (c << 5)][tl];
                const float iv = __expf(-lv);
                const float xx = xv * xv;
                const float e  = fmaf(xv * mu, -2.0f, xx);   // x^2 - 2*x*mu
                accP   = fmaf(e, iv, accP);
                sS[c] += iv;
                sT[c]  = fmaf(mu, iv, sT[c]);
                sX[c] += xv;
                sXX[c] += xx;
            }
        }
        __syncthreads();
    }

    // ---- cross-warp reduce per-d accumulators ----
    #pragma unroll
    for (int c = 0; c < 2; ++c) {
        red[0][w][lane + (c << 5)] = sX[c];
        red[1][w][lane + (c << 5)] = sXX[c];
        red[2][w][lane + (c << 5)] = sS[c];
        red[3][w][lane + (c << 5)] = sT[c];
    }
    #pragma unroll
    for (int o = 16; o; o >>= 1) accP += __shfl_xor_sync(0xffffffffu, accP, o);
    if (lane == 0) spc[w] = accP;
    __syncthreads();

    {
        const int a  = tid >> 6;      // accumulator 0..3
        const int dd = tid & 63;      // d within chunk
        float s = 0.f;
        #pragma unroll
        for (int ww = 0; ww < 8; ++ww) s += red[a][ww][dd];
        // [a][slice][d] layout: coalesced across tid (dd contiguous per warp)
        gPart[(a * NSLICE + slice) * DD + dc + dd] = s;
    }
    if (tid == 0) {
        float s = 0.f;
        #pragma unroll
        for (int ww = 0; ww < 8; ++ww) s += spc[ww];
        gP[bid] = s;
    }
}

// Stage 2: reduce the 128 slice-partials for each (a,d) pair, in double.
// 16 blocks x 128 threads = 2048 threads = one thread per (a,d).
// Reads are coalesced: within a warp, d is contiguous.
__global__ __launch_bounds__(128) void club_reduce_kernel()
{
    const int gt = blockIdx.x * 128 + threadIdx.x;   // 0..2047
    const int a  = gt >> 9;
    const int d  = gt & 511;
    const float* p = &gPart[(a * NSLICE) * DD + d];
    double s = 0.0;
    #pragma unroll 8
    for (int sl = 0; sl < NSLICE; ++sl) s += (double)p[(size_t)sl * DD];
    gAcc[a * DD + d] = s;
}

// Stage 3: tiny single-block finalize (reads 20 KB).
__global__ __launch_bounds__(512) void club_final_kernel(float* __restrict__ out)
{
    __shared__ double sd[512];
    __shared__ double sp[512];
    const int tid = threadIdx.x;   // tid == feature d

    const double X  = gAcc[0 * DD + tid];
    const double XX = gAcc[1 * DD + tid];
    const double S  = gAcc[2 * DD + tid];
    const double T  = gAcc[3 * DD + tid];

    sd[tid] = XX * S - 2.0 * X * T;
    sp[tid] = (double)gP[tid] + (double)gP[tid + 512];
    __syncthreads();

    #pragma unroll
    for (int o = 256; o; o >>= 1) {
        if (tid < o) { sd[tid] += sd[tid + o]; sp[tid] += sp[tid + o]; }
        __syncthreads();
    }
    if (tid == 0) {
        const double N = (double)NTOK;
        const double res = (-0.5 * sp[0] + 0.5 * sd[0] / N) / N;
        out[0] = (float)res;
    }
}

extern "C" void kernel_launch(void* const* d_in, const int* in_sizes, int n_in,
                              void* d_out, int out_size)
{
    const float* x   = (const float*)d_in[0];
    const float* pmu = (const float*)d_in[1];
    const float* plv = (const float*)d_in[2];
    float* out = (float*)d_out;

    club_main_kernel<<<1024, 256>>>(x, pmu, plv);
    club_reduce_kernel<<<16, 128>>>();
    club_final_kernel<<<1, 512>>>(out);
}

// round 4
// speedup vs baseline: 5.2593x; 1.0425x over previous
#include <cuda_runtime.h>
#include <cuda_bf16.h>

// CLUB loss, single-pass formulation.
//   result = ( -0.5*P + 0.5/N * sum_d [ X2_d*S_d - 2*X_d*T_d ] ) / N
// with  P    = sum_{i,d} (x^2 - 2*x*mu) * exp(-lv)
//       X_d  = sum_i x,   X2_d = sum_i x^2
//       S_d  = sum_i exp(-lv),   T_d = sum_i mu*exp(-lv)
// (The mu^2 terms cancel between positive and negative.)
//
// Shapes: x (16,512,32,32) f32, p_mu (16384,512) f32, p_logvar (16384,512) f32.

#define NB   16
#define DD   512
#define HW   1024
#define NTOK (NB * HW)          // 16384
#define NSLICE 128
#define PITCH 129               // smem tile pitch (floats); 129 % 32 == 1

// Stateless per-launch scratch (fully overwritten each launch).
// gPart layout: [a][slice][d]  (d innermost -> coalesced stage-2 reads)
__device__ float        gPart[4 * NSLICE * DD];   // 1 MB
__device__ float        gP[1024];                 // per-block scalar partials
__device__ double       gAcc[4 * DD];
__device__ unsigned int gTicket;                  // reset to 0 by last block each launch

// Grid: 1024 blocks = 8 feature-chunks (64 each) x 128 token-slices (128 each).
__global__ __launch_bounds__(256) void club_main_kernel(
    const float* __restrict__ x,
    const float* __restrict__ pmu,
    const float* __restrict__ plv)
{
    __shared__ float xs[64 * PITCH];      // x tile: [feature][token], 33 KB
    __shared__ float red[4][8][64];       // cross-warp reduction buffer
    __shared__ float spc[8];

    const int tid  = threadIdx.x;
    const int w    = tid >> 5;
    const int lane = tid & 31;
    const int q    = lane & 15;           // float4 feature column (features q*4..q*4+3)
    const int th   = lane >> 4;           // token parity within pass
    const int bid  = blockIdx.x;

    const int dc    = (bid & 7) << 6;     // feature-chunk base (0..448)
    const int slice = bid >> 3;           // token-slice index  (0..127)
    const int i0    = slice << 7;         // first global token of slice
    const int b     = i0 >> 10;           // batch (slice never crosses batch)
    const int hw0   = i0 & 1023;
    const float* xb = x + ((size_t)((b << 9) + dc) << 10) + hw0;   // x[b, dc, hw0]

    // ---- stage x tile: 64 feature-rows x 128 tokens (32 float4 cols) ----
    // Warp covers 4 rows x 8 float4-cols -> conflict-free STS, 512B/row-chunk LDG.
    #pragma unroll
    for (int k = 0; k < 8; ++k) {
        const int qq  = tid + (k << 8);        // 0..2047
        const int c4l = qq & 7;
        const int row = (qq >> 3) & 63;
        const int c4h = qq >> 9;
        const int col = (c4h << 3) + c4l;      // float4 column 0..31
        float4 v = reinterpret_cast<const float4*>(xb + (size_t)row * HW)[col];
        float* d = &xs[row * PITCH + (col << 2)];
        d[0] = v.x; d[1] = v.y; d[2] = v.z; d[3] = v.w;
    }
    __syncthreads();

    // ---- main loop: warp w owns tokens [16w, 16w+16); pass p covers 2 tokens ----
    float sX[4]  = {0.f, 0.f, 0.f, 0.f};
    float sXX[4] = {0.f, 0.f, 0.f, 0.f};
    float sS[4]  = {0.f, 0.f, 0.f, 0.f};
    float sT[4]  = {0.f, 0.f, 0.f, 0.f};
    float accP   = 0.f;

    const int tbase = (w << 4) + th;                       // first token of this thread
    const float* mp = pmu + (size_t)(i0 + tbase) * DD + dc + (q << 2);
    const float* lp = plv + (size_t)(i0 + tbase) * DD + dc + (q << 2);

    float4 mv  = *reinterpret_cast<const float4*>(mp);
    float4 lv4 = *reinterpret_cast<const float4*>(lp);

    #pragma unroll
    for (int p = 0; p < 8; ++p) {
        float4 mn = make_float4(0.f, 0.f, 0.f, 0.f);
        float4 ln = make_float4(0.f, 0.f, 0.f, 0.f);
        if (p < 7) {                                       // prefetch next pass
            mn = *reinterpret_cast<const float4*>(mp + (size_t)(2 * DD) * (p + 1));
            ln = *reinterpret_cast<const float4*>(lp + (size_t)(2 * DD) * (p + 1));
        }
        const int tl = tbase + (p << 1);
        const float* xrow = &xs[(q << 2) * PITCH + tl];
        float xv[4];
        xv[0] = xrow[0];
        xv[1] = xrow[PITCH];
        xv[2] = xrow[2 * PITCH];
        xv[3] = xrow[3 * PITCH];
        const float mm[4] = {mv.x, mv.y, mv.z, mv.w};
        const float ll[4] = {lv4.x, lv4.y, lv4.z, lv4.w};
        #pragma unroll
        for (int j = 0; j < 4; ++j) {
            const float iv = __expf(-ll[j]);
            const float xx = xv[j] * xv[j];
            const float e  = fmaf(xv[j] * mm[j], -2.0f, xx);   // x^2 - 2*x*mu
            accP   = fmaf(e, iv, accP);
            sS[j] += iv;
            sT[j]  = fmaf(mm[j], iv, sT[j]);
            sX[j] += xv[j];
            sXX[j] += xx;
        }
        mv = mn; lv4 = ln;
    }

    // ---- combine the two token-halves (lane ^ 16 holds same features) ----
    #pragma unroll
    for (int j = 0; j < 4; ++j) {
        sX[j]  += __shfl_xor_sync(0xffffffffu, sX[j],  16);
        sXX[j] += __shfl_xor_sync(0xffffffffu, sXX[j], 16);
        sS[j]  += __shfl_xor_sync(0xffffffffu, sS[j],  16);
        sT[j]  += __shfl_xor_sync(0xffffffffu, sT[j],  16);
    }
    #pragma unroll
    for (int o = 16; o; o >>= 1) accP += __shfl_xor_sync(0xffffffffu, accP, o);

    if (lane < 16) {
        #pragma unroll
        for (int j = 0; j < 4; ++j) {
            red[0][w][(q << 2) + j] = sX[j];
            red[1][w][(q << 2) + j] = sXX[j];
            red[2][w][(q << 2) + j] = sS[j];
            red[3][w][(q << 2) + j] = sT[j];
        }
    }
    if (lane == 0) spc[w] = accP;
    __syncthreads();

    {
        const int a  = tid >> 6;      // accumulator 0..3
        const int dd = tid & 63;      // feature within chunk
        float s = 0.f;
        #pragma unroll
        for (int ww = 0; ww < 8; ++ww) s += red[a][ww][dd];
        gPart[(a * NSLICE + slice) * DD + dc + dd] = s;   // coalesced
    }
    if (tid == 0) {
        float s = 0.f;
        #pragma unroll
        for (int ww = 0; ww < 8; ++ww) s += spc[ww];
        gP[bid] = s;
    }
}

// Stage 2 + finalize fused via last-block ticket.
// 16 blocks x 128 threads: one thread per (a,d) pair, double-sum over 128 slices.
__global__ __launch_bounds__(128) void club_reduce_final(float* __restrict__ out)
{
    const int tid = threadIdx.x;
    const int gt  = blockIdx.x * 128 + tid;     // 0..2047
    const int a   = gt >> 9;
    const int d   = gt & 511;

    const float* p = &gPart[(a * NSLICE) * DD + d];
    double s = 0.0;
    #pragma unroll 8
    for (int sl = 0; sl < NSLICE; ++sl) s += (double)p[(size_t)sl * DD];
    gAcc[a * DD + d] = s;

    __shared__ bool amLast;
    __threadfence();
    if (tid == 0) {
        unsigned v = atomicAdd(&gTicket, 1u);
        amLast = (v == 15u);
    }
    __syncthreads();
    if (!amLast) return;

    // Last block: combine. volatile -> bypass L1, see other blocks' gAcc writes.
    volatile double* vAcc = gAcc;
    double term = 0.0, psum = 0.0;
    #pragma unroll
    for (int k = 0; k < 4; ++k) {
        const int dd = tid + (k << 7);
        const double X  = vAcc[0 * DD + dd];
        const double XX = vAcc[1 * DD + dd];
        const double S  = vAcc[2 * DD + dd];
        const double T  = vAcc[3 * DD + dd];
        term += XX * S - 2.0 * X * T;
    }
    #pragma unroll
    for (int k = 0; k < 8; ++k) psum += (double)gP[tid + (k << 7)];

    // block reduce (4 warps)
    #pragma unroll
    for (int o = 16; o; o >>= 1) {
        term += __shfl_xor_sync(0xffffffffu, term, o);
        psum += __shfl_xor_sync(0xffffffffu, psum, o);
    }
    __shared__ double sd[4], sp[4];
    const int wz = tid >> 5;
    if ((tid & 31) == 0) { sd[wz] = term; sp[wz] = psum; }
    __syncthreads();
    if (tid == 0) {
        const double td = sd[0] + sd[1] + sd[2] + sd[3];
        const double tp = sp[0] + sp[1] + sp[2] + sp[3];
        const double N  = (double)NTOK;
        out[0] = (float)((-0.5 * tp + 0.5 * td / N) / N);
        gTicket = 0u;                 // restore invariant for next replay
    }
}

extern "C" void kernel_launch(void* const* d_in, const int* in_sizes, int n_in,
                              void* d_out, int out_size)
{
    const float* x   = (const float*)d_in[0];
    const float* pmu = (const float*)d_in[1];
    const float* plv = (const float*)d_in[2];
    float* out = (float*)d_out;

    club_main_kernel<<<1024, 256>>>(x, pmu, plv);
    club_reduce_final<<<16, 128>>>(out);
}

// round 5
// speedup vs baseline: 5.5234x; 1.0502x over previous
#include <cuda_runtime.h>
#include <cuda_bf16.h>

// CLUB loss, single-pass formulation.
//   result = ( -0.5*P + 0.5/N * sum_d [ X2_d*S_d - 2*X_d*T_d ] ) / N
// with  P    = sum_{i,d} (x^2 - 2*x*mu) * exp(-lv)
//       X_d  = sum_i x,   X2_d = sum_i x^2
//       S_d  = sum_i exp(-lv),   T_d = sum_i mu*exp(-lv)
// (The mu^2 terms cancel between positive and negative.)
//
// Shapes: x (16,512,32,32) f32, p_mu (16384,512) f32, p_logvar (16384,512) f32.

#define NB   16
#define DD   512
#define HW   1024
#define NTOK (NB * HW)          // 16384
#define NSLICE 128
#define PITCH 129               // smem tile pitch (floats); 129 % 32 == 1

// Stateless per-launch scratch (fully overwritten each launch).
// gPart layout: [a][slice][d]  (d innermost -> coalesced stage-2 reads)
__device__ float        gPart[4 * NSLICE * DD];   // 1 MB
__device__ float        gP[1024];                 // per-block scalar partials
__device__ double       gAcc2[4 * 4 * DD];        // [a][slice-quarter][d]
__device__ unsigned int gTicket;                  // reset to 0 by last block each launch

// Grid: 1024 blocks = 8 feature-chunks (64 each) x 128 token-slices (128 each).
__global__ __launch_bounds__(256) void club_main_kernel(
    const float* __restrict__ x,
    const float* __restrict__ pmu,
    const float* __restrict__ plv)
{
    __shared__ float xs[64 * PITCH];      // x tile: [feature][token], 33 KB
    __shared__ float red[4][8][64];       // cross-warp reduction buffer
    __shared__ float spc[8];

    const int tid  = threadIdx.x;
    const int w    = tid >> 5;
    const int lane = tid & 31;
    const int q    = lane & 15;           // float4 feature column (features q*4..q*4+3)
    const int th   = lane >> 4;           // token parity within pass
    const int bid  = blockIdx.x;

    const int dc    = (bid & 7) << 6;     // feature-chunk base (0..448)
    const int slice = bid >> 3;           // token-slice index  (0..127)
    const int i0    = slice << 7;         // first global token of slice
    const int b     = i0 >> 10;           // batch (slice never crosses batch)
    const int hw0   = i0 & 1023;
    const float* xb = x + ((size_t)((b << 9) + dc) << 10) + hw0;   // x[b, dc, hw0]

    // ---- stage x tile: 64 feature-rows x 128 tokens (32 float4 cols) ----
    #pragma unroll
    for (int k = 0; k < 8; ++k) {
        const int qq  = tid + (k << 8);        // 0..2047
        const int c4l = qq & 7;
        const int row = (qq >> 3) & 63;
        const int c4h = qq >> 9;
        const int col = (c4h << 3) + c4l;      // float4 column 0..31
        float4 v = reinterpret_cast<const float4*>(xb + (size_t)row * HW)[col];
        float* d = &xs[row * PITCH + (col << 2)];
        d[0] = v.x; d[1] = v.y; d[2] = v.z; d[3] = v.w;
    }
    __syncthreads();

    // ---- main loop: warp w owns tokens [16w, 16w+16); pass p covers 2 tokens ----
    float sX[4]  = {0.f, 0.f, 0.f, 0.f};
    float sXX[4] = {0.f, 0.f, 0.f, 0.f};
    float sS[4]  = {0.f, 0.f, 0.f, 0.f};
    float sT[4]  = {0.f, 0.f, 0.f, 0.f};
    float accP   = 0.f;

    const int tbase = (w << 4) + th;                       // first token of this thread
    const float* mp = pmu + (size_t)(i0 + tbase) * DD + dc + (q << 2);
    const float* lp = plv + (size_t)(i0 + tbase) * DD + dc + (q << 2);

    float4 mv  = *reinterpret_cast<const float4*>(mp);
    float4 lv4 = *reinterpret_cast<const float4*>(lp);

    #pragma unroll
    for (int p = 0; p < 8; ++p) {
        float4 mn = make_float4(0.f, 0.f, 0.f, 0.f);
        float4 ln = make_float4(0.f, 0.f, 0.f, 0.f);
        if (p < 7) {                                       // prefetch next pass
            mn = *reinterpret_cast<const float4*>(mp + (size_t)(2 * DD) * (p + 1));
            ln = *reinterpret_cast<const float4*>(lp + (size_t)(2 * DD) * (p + 1));
        }
        const int tl = tbase + (p << 1);
        const float* xrow = &xs[(q << 2) * PITCH + tl];
        float xv[4];
        xv[0] = xrow[0];
        xv[1] = xrow[PITCH];
        xv[2] = xrow[2 * PITCH];
        xv[3] = xrow[3 * PITCH];
        const float mm[4] = {mv.x, mv.y, mv.z, mv.w};
        const float ll[4] = {lv4.x, lv4.y, lv4.z, lv4.w};
        #pragma unroll
        for (int j = 0; j < 4; ++j) {
            const float iv = __expf(-ll[j]);
            const float xx = xv[j] * xv[j];
            const float e  = fmaf(xv[j] * mm[j], -2.0f, xx);   // x^2 - 2*x*mu
            accP   = fmaf(e, iv, accP);
            sS[j] += iv;
            sT[j]  = fmaf(mm[j], iv, sT[j]);
            sX[j] += xv[j];
            sXX[j] += xx;
        }
        mv = mn; lv4 = ln;
    }

    // ---- combine the two token-halves (lane ^ 16 holds same features) ----
    #pragma unroll
    for (int j = 0; j < 4; ++j) {
        sX[j]  += __shfl_xor_sync(0xffffffffu, sX[j],  16);
        sXX[j] += __shfl_xor_sync(0xffffffffu, sXX[j], 16);
        sS[j]  += __shfl_xor_sync(0xffffffffu, sS[j],  16);
        sT[j]  += __shfl_xor_sync(0xffffffffu, sT[j],  16);
    }
    #pragma unroll
    for (int o = 16; o; o >>= 1) accP += __shfl_xor_sync(0xffffffffu, accP, o);

    if (lane < 16) {
        #pragma unroll
        for (int j = 0; j < 4; ++j) {
            red[0][w][(q << 2) + j] = sX[j];
            red[1][w][(q << 2) + j] = sXX[j];
            red[2][w][(q << 2) + j] = sS[j];
            red[3][w][(q << 2) + j] = sT[j];
        }
    }
    if (lane == 0) spc[w] = accP;
    __syncthreads();

    {
        const int a  = tid >> 6;      // accumulator 0..3
        const int dd = tid & 63;      // feature within chunk
        float s = 0.f;
        #pragma unroll
        for (int ww = 0; ww < 8; ++ww) s += red[a][ww][dd];
        gPart[(a * NSLICE + slice) * DD + dc + dd] = s;   // coalesced
    }
    if (tid == 0) {
        float s = 0.f;
        #pragma unroll
        for (int ww = 0; ww < 8; ++ww) s += spc[ww];
        gP[bid] = s;
    }
}

// Stage 2 + finalize, fused via last-block ticket.
// 64 blocks x 128 threads. Block b: a = b>>4, slice-quarter sq = (b>>2)&3,
// d-range dr = b&3. Each thread sums 32 slices for one d, with 4 independent
// double accumulators (chain length 8).
__global__ __launch_bounds__(128) void club_reduce_final(float* __restrict__ out)
{
    const int tid = threadIdx.x;
    const int b   = blockIdx.x;
    const int a   = b >> 4;
    const int sq  = (b >> 2) & 3;
    const int dr  = b & 3;
    const int d   = (dr << 7) + tid;

    const float* p = &gPart[((a * NSLICE) + (sq << 5)) * DD + d];
    double acc0 = 0.0, acc1 = 0.0, acc2 = 0.0, acc3 = 0.0;
    #pragma unroll
    for (int k = 0; k < 8; ++k) {
        const float* pk = p + (size_t)(k << 2) * DD;
        acc0 += (double)pk[0];
        acc1 += (double)pk[(size_t)DD];
        acc2 += (double)pk[(size_t)2 * DD];
        acc3 += (double)pk[(size_t)3 * DD];
    }
    gAcc2[((a << 2) + sq) * DD + d] = (acc0 + acc1) + (acc2 + acc3);

    __shared__ bool amLast;
    __threadfence();
    if (tid == 0) {
        unsigned v = atomicAdd(&gTicket, 1u);
        amLast = (v == 63u);
    }
    __syncthreads();
    if (!amLast) return;

    // Last block: combine. volatile -> bypass L1, see other blocks' writes.
    volatile double* vA = gAcc2;
    double term = 0.0, psum = 0.0;
    #pragma unroll
    for (int k = 0; k < 4; ++k) {
        const int dd = tid + (k << 7);
        double A[4];
        #pragma unroll
        for (int aa = 0; aa < 4; ++aa) {
            A[aa] = vA[((aa << 2) + 0) * DD + dd] + vA[((aa << 2) + 1) * DD + dd]
                  + vA[((aa << 2) + 2) * DD + dd] + vA[((aa << 2) + 3) * DD + dd];
        }
        term += A[1] * A[2] - 2.0 * A[0] * A[3];   // XX*S - 2*X*T
    }
    #pragma unroll
    for (int k = 0; k < 8; ++k) psum += (double)gP[tid + (k << 7)];

    #pragma unroll
    for (int o = 16; o; o >>= 1) {
        term += __shfl_xor_sync(0xffffffffu, term, o);
        psum += __shfl_xor_sync(0xffffffffu, psum, o);
    }
    __shared__ double sd[4], sp[4];
    const int wz = tid >> 5;
    if ((tid & 31) == 0) { sd[wz] = term; sp[wz] = psum; }
    __syncthreads();
    if (tid == 0) {
        const double td = sd[0] + sd[1] + sd[2] + sd[3];
        const double tp = sp[0] + sp[1] + sp[2] + sp[3];
        const double N  = (double)NTOK;
        out[0] = (float)((-0.5 * tp + 0.5 * td / N) / N);
        gTicket = 0u;                 // restore invariant for next replay
    }
}

extern "C" void kernel_launch(void* const* d_in, const int* in_sizes, int n_in,
                              void* d_out, int out_size)
{
    const float* x   = (const float*)d_in[0];
    const float* pmu = (const float*)d_in[1];
    const float* plv = (const float*)d_in[2];
    float* out = (float*)d_out;

    club_main_kernel<<<1024, 256>>>(x, pmu, plv);
    club_reduce_final<<<64, 128>>>(out);
}